// round 13
// baseline (speedup 1.0000x reference)
#include <cuda_runtime.h>
#include <math.h>

// Problem constants
namespace {
constexpr int Gd = 4, Td = 4096, Dd = 2048, Ed = 64, Cd = 128;
constexpr int GT = Gd * Td;                         // 16384 tokens
constexpr long long GTEC = (long long)GT * Ed * Cd; // 134217728
constexpr int NB_G = 128;                           // GEMM blocks (128 rows each)
constexpr int NB_Z = 320;                           // zero-only blocks
constexpr int NBTOT = NB_G + NB_Z;                  // 448
constexpr long long CHUNK_Z = 46080;                // float4 per zero block (180/thread @256)
constexpr long long NF = CHUNK_Z * NB_Z;            // 14,745,600 float4 fused (~236MB)
}

// Scratch (fully overwritten every launch -> deterministic)
__device__ float g_gate1[GT];
__device__ float g_gate2[GT];
__device__ int   g_idx[GT];                // idx1 | idx2<<8
__device__ float g_sumP_part[NB_G][Ed];    // per-block sum of probs per expert
__device__ float g_z_part[NB_G];           // per-block z-loss partial
__device__ int   g_cnt[Gd * Ed];           // tokens per (group, expert) in top-2

// ---------------------------------------------------------------------------
// Kernel 1 (fused): blocks [0,NB_G): 128-row x 64-expert GEMM, K=2048.
// 256 threads / block -> 2 warps per SMSP during the GEMM phase (latency
// hiding); each thread computes a 4x8 sub-tile. Accumulation chain per output
// is k=0..2047 sequential — IDENTICAL to R3-R9 (bit-stable; never split K).
// Blocks [NB_G,NBTOT): zero-fill contiguous chunks of out[0:NF).
// ---------------------------------------------------------------------------
__global__ void __launch_bounds__(256) k_main(const float* __restrict__ X,
                                               const float* __restrict__ W,
                                               const float* __restrict__ bias_v,
                                               float* __restrict__ out) {
    const int tid = threadIdx.x;
    const int bid = blockIdx.x;

    if (bid >= NB_G) {
        // ---------- zero-fill role: contiguous chunk ----------
        const float4 z4 = make_float4(0.f, 0.f, 0.f, 0.f);
        float4* o4 = (float4*)out;
        long long base = (long long)(bid - NB_G) * CHUNK_Z + tid;
#pragma unroll 4
        for (int k = 0; k < (int)(CHUNK_Z / 256); k++)
            o4[base + (long long)k * 256] = z4;
        return;
    }

    // ---------- GEMM role ----------
    // smem: As[16][128] (2048f) + Bsd[16][128] (2048f, B stored as (b,b) pairs)
    // unioned with S[128][65] (8320f) for the epilogue.
    __shared__ float smem_raw[128 * 65];
    __shared__ float rowz[128];
    float (*As)[128]  = (float(*)[128])smem_raw;           // [16][128]
    float (*Bsd)[128] = (float(*)[128])(smem_raw + 2048);  // [16][128]
    float (*S)[65]    = (float(*)[65])smem_raw;            // [128][65]

    const int m0 = bid * 128;
    const int tx = tid & 7;    // 8 col-groups -> 8 cols each
    const int ty = tid >> 3;   // 32 row-groups -> 4 rows each (2 row-pairs)

    unsigned long long acc2[2][8];
#pragma unroll
    for (int i = 0; i < 2; i++)
#pragma unroll
        for (int j = 0; j < 8; j++) acc2[i][j] = 0ull;

    // tile-load mapping: X 512 float4s -> 2/thread (rows rA, rA+64);
    //                    W 256 float4s -> 1/thread (dup-stored)
    const int rA = tid >> 2, qA = tid & 3;
    const int kwb = tid >> 4, e4 = tid & 15;
    const float* Xb = X + (long long)m0 * Dd + qA * 4;
    const float* Wb = W + (long long)kwb * Ed + e4 * 4;

    float4 xa0, xa1, wbv;
    xa0 = *(const float4*)(Xb + (long long)rA * Dd);
    xa1 = *(const float4*)(Xb + (long long)(rA + 64) * Dd);
    wbv = *(const float4*)(Wb);

    As[qA * 4 + 0][rA] = xa0.x; As[qA * 4 + 1][rA] = xa0.y;
    As[qA * 4 + 2][rA] = xa0.z; As[qA * 4 + 3][rA] = xa0.w;
    As[qA * 4 + 0][rA + 64] = xa1.x; As[qA * 4 + 1][rA + 64] = xa1.y;
    As[qA * 4 + 2][rA + 64] = xa1.z; As[qA * 4 + 3][rA + 64] = xa1.w;
    {
        float4 d0 = make_float4(wbv.x, wbv.x, wbv.y, wbv.y);
        float4 d1 = make_float4(wbv.z, wbv.z, wbv.w, wbv.w);
        *(float4*)&Bsd[kwb][e4 * 8]     = d0;
        *(float4*)&Bsd[kwb][e4 * 8 + 4] = d1;
    }
    __syncthreads();

    constexpr int NTILES = Dd / 16;   // 128
    for (int t = 0; t < NTILES; t++) {
        if (t + 1 < NTILES) {
            const float* Xo = Xb + (t + 1) * 16;
            xa0 = *(const float4*)(Xo + (long long)rA * Dd);
            xa1 = *(const float4*)(Xo + (long long)(rA + 64) * Dd);
            wbv = *(const float4*)(Wb + (long long)(t + 1) * 16 * Ed);
        }
#pragma unroll
        for (int kk = 0; kk < 16; kk++) {
            ulonglong2 aA = *(const ulonglong2*)&As[kk][ty * 4];
            unsigned long long ap[2] = {aA.x, aA.y};
            ulonglong2 b0 = *(const ulonglong2*)&Bsd[kk][tx * 16];
            ulonglong2 b1 = *(const ulonglong2*)&Bsd[kk][tx * 16 + 4];
            ulonglong2 b2 = *(const ulonglong2*)&Bsd[kk][tx * 16 + 8];
            ulonglong2 b3 = *(const ulonglong2*)&Bsd[kk][tx * 16 + 12];
            unsigned long long bd[8] = {b0.x, b0.y, b1.x, b1.y,
                                        b2.x, b2.y, b3.x, b3.y};
#pragma unroll
            for (int i = 0; i < 2; i++)
#pragma unroll
                for (int j = 0; j < 8; j++)
                    asm("fma.rn.f32x2 %0, %1, %2, %0;"
                        : "+l"(acc2[i][j]) : "l"(ap[i]), "l"(bd[j]));
        }
        __syncthreads();
        if (t + 1 < NTILES) {
            As[qA * 4 + 0][rA] = xa0.x; As[qA * 4 + 1][rA] = xa0.y;
            As[qA * 4 + 2][rA] = xa0.z; As[qA * 4 + 3][rA] = xa0.w;
            As[qA * 4 + 0][rA + 64] = xa1.x; As[qA * 4 + 1][rA + 64] = xa1.y;
            As[qA * 4 + 2][rA + 64] = xa1.z; As[qA * 4 + 3][rA + 64] = xa1.w;
            float4 d0 = make_float4(wbv.x, wbv.x, wbv.y, wbv.y);
            float4 d1 = make_float4(wbv.z, wbv.z, wbv.w, wbv.w);
            *(float4*)&Bsd[kwb][e4 * 8]     = d0;
            *(float4*)&Bsd[kwb][e4 * 8 + 4] = d1;
            __syncthreads();
        }
    }

    // unpack accumulators (+bias) into S as logits (As/Bsd dead now)
    float bcol[8];
    *(float4*)&bcol[0] = *(const float4*)&bias_v[tx * 8];
    *(float4*)&bcol[4] = *(const float4*)&bias_v[tx * 8 + 4];
#pragma unroll
    for (int i = 0; i < 2; i++) {
#pragma unroll
        for (int j = 0; j < 8; j++) {
            float lo, hi;
            asm("mov.b64 {%0,%1}, %2;" : "=f"(lo), "=f"(hi) : "l"(acc2[i][j]));
            S[ty * 4 + 2 * i + 0][tx * 8 + j] = lo + bcol[j];
            S[ty * 4 + 2 * i + 1][tx * 8 + j] = hi + bcol[j];
        }
    }
    __syncthreads();

    // per-row softmax / top-2 / z partial (128 rows, threads 0..127)
    if (tid < 128) {
        const int r = tid;
        const int row = m0 + r;
        float mx = -3.0e38f;
#pragma unroll 8
        for (int e = 0; e < Ed; e++) mx = fmaxf(mx, S[r][e]);
        float sum = 0.f;
        float l1 = -3.0e38f, l2 = -3.0e38f;
        int i1 = 0, i2 = 0;
        for (int e = 0; e < Ed; e++) {
            float L = S[r][e];
            sum += expf(L - mx);
            if (L > l1) { l2 = l1; i2 = i1; l1 = L; i1 = e; }
            else if (L > l2) { l2 = L; i2 = e; }
        }
        float lse = mx + logf(sum);
        float zr = 0.f;
        for (int e = 0; e < Ed; e++) {
            float d = S[r][e] - lse;
            zr += d * d;
        }
        rowz[r] = zr;
        g_gate1[row] = expf(l1 - mx) / sum;
        g_gate2[row] = expf(l2 - mx) / sum;
        g_idx[row] = i1 | (i2 << 8);
        for (int e = 0; e < Ed; e++) S[r][e] = expf(S[r][e] - mx) / sum;
    }
    __syncthreads();

    // column sums of probs -> per-block partials for aux loss
    if (tid < 64) {
        float s = 0.f;
#pragma unroll 8
        for (int r = 0; r < 128; r++) s += S[r][tid];
        g_sumP_part[bid][tid] = s;
    }
    if (tid < 32) {
        float s = rowz[tid] + rowz[tid + 32] + rowz[tid + 64] + rowz[tid + 96];
#pragma unroll
        for (int o = 16; o; o >>= 1) s += __shfl_xor_sync(0xffffffffu, s, o);
        if (tid == 0) g_z_part[bid] = s;
    }
}

// ---------------------------------------------------------------------------
// Kernel 2: per-group BPR sort + capacity assignment + sparse scatter.
// One block per group, 1024 threads.
// ---------------------------------------------------------------------------
__global__ void __launch_bounds__(1024) k_route(float* __restrict__ out) {
    __shared__ unsigned long long keys[4096];  // 32KB (later reused as hist)
    __shared__ unsigned short tok[4096];       // 8KB

    const int tid = threadIdx.x;
    const int g = blockIdx.x;
    const int lane = tid & 31;
    const int warp = tid >> 5;                 // 0..31
    const unsigned lt = (1u << lane) - 1u;

    // keys: descending gate1, ties -> ascending token index (stable)
    for (int i = tid; i < Td; i += 1024) {
        unsigned u = __float_as_uint(g_gate1[g * Td + i]);
        unsigned o = (u >> 31) ? ~u : (u | 0x80000000u);
        keys[i] = (((unsigned long long)(~o)) << 32) | (unsigned)i;
    }
    __syncthreads();

    // bitonic sort ascending (4096 elements)
    for (unsigned k = 2; k <= 4096; k <<= 1) {
        for (unsigned j = k >> 1; j > 0; j >>= 1) {
            for (unsigned i = tid; i < 4096; i += 1024) {
                unsigned ixj = i ^ j;
                if (ixj > i) {
                    unsigned long long a = keys[i], b = keys[ixj];
                    bool up = ((i & k) == 0);
                    if ((a > b) == up) { keys[i] = b; keys[ixj] = a; }
                }
            }
            __syncthreads();
        }
    }

    for (int i = tid; i < Td; i += 1024) tok[i] = (unsigned short)(keys[i] & 0xffffu);
    __syncthreads();

    unsigned short* hist = (unsigned short*)keys;  // [128 chunks][64 experts]
    unsigned* h32 = (unsigned*)keys;

    int tot1 = 0;  // per-expert top-1 totals kept in registers of threads tid<64

    for (int s = 0; s < 2; s++) {
        for (int i = tid; i < 4096; i += 1024) h32[i] = 0u;
        __syncthreads();

        int myE[4], myLr[4], myT[4];
#pragma unroll
        for (int jj = 0; jj < 4; jj++) {
            int c = warp * 4 + jj;          // chunk of 32 sorted positions
            int p = c * 32 + lane;
            int t = tok[p];
            int packed = g_idx[g * Td + t];
            int e = (s == 0) ? (packed & 0xff) : ((packed >> 8) & 0xff);
            unsigned m = __match_any_sync(0xffffffffu, e);
            int lr = __popc(m & lt);
            if ((m & lt) == 0) hist[c * 64 + e] = (unsigned short)__popc(m);
            myE[jj] = e; myLr[jj] = lr; myT[jj] = t;
        }
        __syncthreads();

        // exclusive scan over chunks per expert
        if (tid < 64) {
            int run = (s == 0) ? 0 : tot1;
            for (int c = 0; c < 128; c++) {
                int v = hist[c * 64 + tid];
                hist[c * 64 + tid] = (unsigned short)run;
                run += v;
            }
            if (s == 0) tot1 = run;
            else g_cnt[g * 64 + tid] = run;
        }
        __syncthreads();

        const float* gsrc = (s == 0) ? g_gate1 : g_gate2;
#pragma unroll
        for (int jj = 0; jj < 4; jj++) {
            int c = warp * 4 + jj;
            int pr = (int)hist[c * 64 + myE[jj]] + myLr[jj];
            if (pr < Cd) {
                long long idx = (((long long)(g * Td + myT[jj]) * Ed + myE[jj]) * Cd + pr);
                float gate = gsrc[g * Td + myT[jj]];
                out[idx] = 1.0f;          // dispatch
                out[GTEC + idx] = gate;   // combine
            }
        }
        __syncthreads();
    }
}

// ---------------------------------------------------------------------------
// Kernel 3: finalize aux_loss and z_loss scalars.
// ---------------------------------------------------------------------------
__global__ void __launch_bounds__(64) k_final(float* __restrict__ out) {
    __shared__ float red[4];
    int tid = threadIdx.x;  // 64 threads
    float term = 0.f;
    for (int g = 0; g < Gd; g++) {
        float sp = 0.f;
        for (int bb = 0; bb < 32; bb++) sp += g_sumP_part[g * 32 + bb][tid];
        term += (float)g_cnt[g * 64 + tid] * sp;
    }
    float z = g_z_part[tid] + g_z_part[tid + 64];
#pragma unroll
    for (int o = 16; o; o >>= 1) {
        term += __shfl_xor_sync(0xffffffffu, term, o);
        z += __shfl_xor_sync(0xffffffffu, z, o);
    }
    if ((tid & 31) == 0) { red[tid >> 5] = term; red[2 + (tid >> 5)] = z; }
    __syncthreads();
    if (tid == 0) {
        float T2 = red[0] + red[1];
        float Z2 = red[2] + red[3];
        out[2 * GTEC]     = T2 * (64.0f / (4.0f * 4096.0f * 4096.0f));
        out[2 * GTEC + 1] = Z2 * (1.0f / (4.0f * 4096.0f * 64.0f));
    }
}

// ---------------------------------------------------------------------------
extern "C" void kernel_launch(void* const* d_in, const int* in_sizes, int n_in,
                              void* d_out, int out_size) {
    const float* X = (const float*)d_in[0];
    const float* W = (const float*)d_in[1];
    const float* b = (const float*)d_in[2];
    float* out = (float*)d_out;

    // k_main: GEMM + fused zero of the first NF float4s.
    k_main<<<NBTOT, 256>>>(X, W, b, out);

    // Driver-optimized memset node zeroes the remainder (~6.2 TB/s measured).
    const size_t fused_bytes = (size_t)NF * 16;
    const size_t total_bytes = (size_t)out_size * 4;
    cudaMemsetAsync((char*)d_out + fused_bytes, 0, total_bytes - fused_bytes, 0);

    k_route<<<Gd, 1024>>>(out);
    k_final<<<1, 64>>>(out);
}

// round 14
// speedup vs baseline: 3.4933x; 3.4933x over previous
#include <cuda_runtime.h>
#include <math.h>

// Problem constants
namespace {
constexpr int Gd = 4, Td = 4096, Dd = 2048, Ed = 64, Cd = 128;
constexpr int GT = Gd * Td;                         // 16384 tokens
constexpr long long GTEC = (long long)GT * Ed * Cd; // 134217728
constexpr int NB_G = 128;                           // GEMM blocks (128 rows each)
constexpr int NB_Z = 128;                           // TMA zero-stream blocks
constexpr int NBTOT = NB_G + NB_Z;                  // 256
constexpr int CHUNK_BYTES = 16384;                  // one bulk store = 16KB
constexpr int CHUNKS_PER_BLK = 512;                 // 8MB per zero block
// NB_Z * CHUNKS_PER_BLK * CHUNK_BYTES = 1,073,741,824 = 2*GTEC*4 bytes exactly
}

// Scratch (fully overwritten every launch -> deterministic)
__device__ float g_gate1[GT];
__device__ float g_gate2[GT];
__device__ int   g_idx[GT];                // idx1 | idx2<<8
__device__ float g_sumP_part[NB_G][Ed];    // per-block sum of probs per expert
__device__ float g_z_part[NB_G];           // per-block z-loss partial
__device__ int   g_cnt[Gd * Ed];           // tokens per (group, expert) in top-2

// ---------------------------------------------------------------------------
// Kernel 1 (fused): blocks [0,NB_G): 128-row x 64-expert GEMM, K=2048,
// 8x8 register tile/thread (bit-stable k=0..2047 chain — NEVER split K).
// Blocks [NB_G,NBTOT): zero the output via cp.async.bulk SMEM->GMEM stores
// (async-proxy path, ~LTS-cap bandwidth, near-zero SM issue cost) running
// concurrently with the GEMM blocks.
// ---------------------------------------------------------------------------
__global__ void __launch_bounds__(128) k_main(const float* __restrict__ X,
                                               const float* __restrict__ W,
                                               const float* __restrict__ bias_v,
                                               float* __restrict__ out) {
    const int tid = threadIdx.x;
    const int bid = blockIdx.x;

    // smem: GEMM uses As/Bs unioned with S; zero role reuses first 16KB as
    // a zero page for bulk stores.
    __shared__ float smem_raw[128 * 65];
    __shared__ float rowz[128];

    if (bid >= NB_G) {
        // ---------- zero-stream role: async-proxy bulk stores ----------
        for (int i = tid; i < CHUNK_BYTES / 4; i += 128) smem_raw[i] = 0.f;
        __syncthreads();
        if (tid == 0) {
            asm volatile("fence.proxy.async.shared::cta;" ::: "memory");
            unsigned int saddr;
            asm("{ .reg .u64 t; cvta.to.shared.u64 t, %1; cvt.u32.u64 %0, t; }"
                : "=r"(saddr) : "l"(smem_raw));
            char* dst = (char*)out +
                        (long long)(bid - NB_G) * CHUNKS_PER_BLK * CHUNK_BYTES;
            const unsigned int csz = CHUNK_BYTES;
            for (int c = 0; c < CHUNKS_PER_BLK; c++) {
                asm volatile(
                    "cp.async.bulk.global.shared::cta.bulk_group [%0], [%1], %2;"
                    :: "l"(dst + (long long)c * CHUNK_BYTES), "r"(saddr), "r"(csz)
                    : "memory");
                if ((c & 7) == 7) {
                    asm volatile("cp.async.bulk.commit_group;" ::: "memory");
                    asm volatile("cp.async.bulk.wait_group.read 4;" ::: "memory");
                }
            }
            asm volatile("cp.async.bulk.commit_group;" ::: "memory");
            asm volatile("cp.async.bulk.wait_group 0;" ::: "memory");
        }
        __syncthreads();
        return;
    }

    // ---------- GEMM role (verbatim R9-verified, bit-stable) ----------
    float (*As)[128]  = (float(*)[128])smem_raw;           // [16][128]
    float (*Bs)[64]   = (float(*)[64])(smem_raw + 2048);   // [16][64]
    float (*S)[65]    = (float(*)[65])smem_raw;            // [128][65]

    const int m0 = bid * 128;
    const int tx = tid & 7;    // 8 cols each
    const int ty = tid >> 3;   // 8 rows each (4 row-pairs)

    unsigned long long acc2[4][8];
#pragma unroll
    for (int i = 0; i < 4; i++)
#pragma unroll
        for (int j = 0; j < 8; j++) acc2[i][j] = 0ull;

    // tile-load mapping (X: 512 float4s -> 4/thread; W: 256 float4s -> 2/thread)
    const int rbase = tid >> 2, qA = tid & 3;
    const int kwb = tid >> 4, e4 = tid & 15;
    const float* Xb = X + (long long)m0 * Dd + qA * 4;
    const float* Wb = W + (long long)kwb * Ed + e4 * 4;

    float4 xa[4], wb[2];
#pragma unroll
    for (int p = 0; p < 4; p++)
        xa[p] = *(const float4*)(Xb + (long long)(p * 32 + rbase) * Dd);
    wb[0] = *(const float4*)(Wb);
    wb[1] = *(const float4*)(Wb + 8 * Ed);

#pragma unroll
    for (int p = 0; p < 4; p++) {
        int r = p * 32 + rbase;
        As[qA * 4 + 0][r] = xa[p].x; As[qA * 4 + 1][r] = xa[p].y;
        As[qA * 4 + 2][r] = xa[p].z; As[qA * 4 + 3][r] = xa[p].w;
    }
    *(float4*)&Bs[kwb][e4 * 4]     = wb[0];
    *(float4*)&Bs[kwb + 8][e4 * 4] = wb[1];
    __syncthreads();

    constexpr int NTILES = Dd / 16;   // 128
    for (int t = 0; t < NTILES; t++) {
        if (t + 1 < NTILES) {
            const float* Xo = Xb + (t + 1) * 16;
#pragma unroll
            for (int p = 0; p < 4; p++)
                xa[p] = *(const float4*)(Xo + (long long)(p * 32 + rbase) * Dd);
            const float* Wo = Wb + (long long)(t + 1) * 16 * Ed;
            wb[0] = *(const float4*)(Wo);
            wb[1] = *(const float4*)(Wo + 8 * Ed);
        }
#pragma unroll
        for (int kk = 0; kk < 16; kk++) {
            ulonglong2 aA = *(const ulonglong2*)&As[kk][ty * 8];
            ulonglong2 aB = *(const ulonglong2*)&As[kk][ty * 8 + 4];
            unsigned long long ap[4] = {aA.x, aA.y, aB.x, aB.y};
            float4 b0 = *(const float4*)&Bs[kk][tx * 8];
            float4 b1 = *(const float4*)&Bs[kk][tx * 8 + 4];
            unsigned long long bd[8];
            asm("mov.b64 %0, {%1,%1};" : "=l"(bd[0]) : "f"(b0.x));
            asm("mov.b64 %0, {%1,%1};" : "=l"(bd[1]) : "f"(b0.y));
            asm("mov.b64 %0, {%1,%1};" : "=l"(bd[2]) : "f"(b0.z));
            asm("mov.b64 %0, {%1,%1};" : "=l"(bd[3]) : "f"(b0.w));
            asm("mov.b64 %0, {%1,%1};" : "=l"(bd[4]) : "f"(b1.x));
            asm("mov.b64 %0, {%1,%1};" : "=l"(bd[5]) : "f"(b1.y));
            asm("mov.b64 %0, {%1,%1};" : "=l"(bd[6]) : "f"(b1.z));
            asm("mov.b64 %0, {%1,%1};" : "=l"(bd[7]) : "f"(b1.w));
#pragma unroll
            for (int i = 0; i < 4; i++)
#pragma unroll
                for (int j = 0; j < 8; j++)
                    asm("fma.rn.f32x2 %0, %1, %2, %0;"
                        : "+l"(acc2[i][j]) : "l"(ap[i]), "l"(bd[j]));
        }
        __syncthreads();
        if (t + 1 < NTILES) {
#pragma unroll
            for (int p = 0; p < 4; p++) {
                int r = p * 32 + rbase;
                As[qA * 4 + 0][r] = xa[p].x; As[qA * 4 + 1][r] = xa[p].y;
                As[qA * 4 + 2][r] = xa[p].z; As[qA * 4 + 3][r] = xa[p].w;
            }
            *(float4*)&Bs[kwb][e4 * 4]     = wb[0];
            *(float4*)&Bs[kwb + 8][e4 * 4] = wb[1];
            __syncthreads();
        }
    }

    // unpack accumulators (+bias) into S as logits (As/Bs dead now)
    float bcol[8];
    *(float4*)&bcol[0] = *(const float4*)&bias_v[tx * 8];
    *(float4*)&bcol[4] = *(const float4*)&bias_v[tx * 8 + 4];
#pragma unroll
    for (int i = 0; i < 4; i++) {
#pragma unroll
        for (int j = 0; j < 8; j++) {
            float lo, hi;
            asm("mov.b64 {%0,%1}, %2;" : "=f"(lo), "=f"(hi) : "l"(acc2[i][j]));
            S[ty * 8 + 2 * i + 0][tx * 8 + j] = lo + bcol[j];
            S[ty * 8 + 2 * i + 1][tx * 8 + j] = hi + bcol[j];
        }
    }
    __syncthreads();

    // per-row softmax / top-2 / z partial (128 rows, one thread per row)
    {
        const int r = tid;
        const int row = m0 + r;
        float mx = -3.0e38f;
#pragma unroll 8
        for (int e = 0; e < Ed; e++) mx = fmaxf(mx, S[r][e]);
        float sum = 0.f;
        float l1 = -3.0e38f, l2 = -3.0e38f;
        int i1 = 0, i2 = 0;
        for (int e = 0; e < Ed; e++) {
            float L = S[r][e];
            sum += expf(L - mx);
            if (L > l1) { l2 = l1; i2 = i1; l1 = L; i1 = e; }
            else if (L > l2) { l2 = L; i2 = e; }
        }
        float lse = mx + logf(sum);
        float zr = 0.f;
        for (int e = 0; e < Ed; e++) {
            float d = S[r][e] - lse;
            zr += d * d;
        }
        rowz[r] = zr;
        g_gate1[row] = expf(l1 - mx) / sum;
        g_gate2[row] = expf(l2 - mx) / sum;
        g_idx[row] = i1 | (i2 << 8);
        for (int e = 0; e < Ed; e++) S[r][e] = expf(S[r][e] - mx) / sum;
    }
    __syncthreads();

    // column sums of probs -> per-block partials for aux loss
    if (tid < 64) {
        float s = 0.f;
#pragma unroll 8
        for (int r = 0; r < 128; r++) s += S[r][tid];
        g_sumP_part[bid][tid] = s;
    }
    if (tid < 32) {
        float s = rowz[tid] + rowz[tid + 32] + rowz[tid + 64] + rowz[tid + 96];
#pragma unroll
        for (int o = 16; o; o >>= 1) s += __shfl_xor_sync(0xffffffffu, s, o);
        if (tid == 0) g_z_part[bid] = s;
    }
}

// ---------------------------------------------------------------------------
// Kernel 2: per-group BPR sort + capacity assignment + sparse scatter.
// One block per group, 1024 threads.
// ---------------------------------------------------------------------------
__global__ void __launch_bounds__(1024) k_route(float* __restrict__ out) {
    __shared__ unsigned long long keys[4096];  // 32KB (later reused as hist)
    __shared__ unsigned short tok[4096];       // 8KB

    const int tid = threadIdx.x;
    const int g = blockIdx.x;
    const int lane = tid & 31;
    const int warp = tid >> 5;                 // 0..31
    const unsigned lt = (1u << lane) - 1u;

    // keys: descending gate1, ties -> ascending token index (stable)
    for (int i = tid; i < Td; i += 1024) {
        unsigned u = __float_as_uint(g_gate1[g * Td + i]);
        unsigned o = (u >> 31) ? ~u : (u | 0x80000000u);
        keys[i] = (((unsigned long long)(~o)) << 32) | (unsigned)i;
    }
    __syncthreads();

    // bitonic sort ascending (4096 elements)
    for (unsigned k = 2; k <= 4096; k <<= 1) {
        for (unsigned j = k >> 1; j > 0; j >>= 1) {
            for (unsigned i = tid; i < 4096; i += 1024) {
                unsigned ixj = i ^ j;
                if (ixj > i) {
                    unsigned long long a = keys[i], b = keys[ixj];
                    bool up = ((i & k) == 0);
                    if ((a > b) == up) { keys[i] = b; keys[ixj] = a; }
                }
            }
            __syncthreads();
        }
    }

    for (int i = tid; i < Td; i += 1024) tok[i] = (unsigned short)(keys[i] & 0xffffu);
    __syncthreads();

    unsigned short* hist = (unsigned short*)keys;  // [128 chunks][64 experts]
    unsigned* h32 = (unsigned*)keys;

    int tot1 = 0;  // per-expert top-1 totals kept in registers of threads tid<64

    for (int s = 0; s < 2; s++) {
        for (int i = tid; i < 4096; i += 1024) h32[i] = 0u;
        __syncthreads();

        int myE[4], myLr[4], myT[4];
#pragma unroll
        for (int jj = 0; jj < 4; jj++) {
            int c = warp * 4 + jj;          // chunk of 32 sorted positions
            int p = c * 32 + lane;
            int t = tok[p];
            int packed = g_idx[g * Td + t];
            int e = (s == 0) ? (packed & 0xff) : ((packed >> 8) & 0xff);
            unsigned m = __match_any_sync(0xffffffffu, e);
            int lr = __popc(m & lt);
            if ((m & lt) == 0) hist[c * 64 + e] = (unsigned short)__popc(m);
            myE[jj] = e; myLr[jj] = lr; myT[jj] = t;
        }
        __syncthreads();

        // exclusive scan over chunks per expert
        if (tid < 64) {
            int run = (s == 0) ? 0 : tot1;
            for (int c = 0; c < 128; c++) {
                int v = hist[c * 64 + tid];
                hist[c * 64 + tid] = (unsigned short)run;
                run += v;
            }
            if (s == 0) tot1 = run;
            else g_cnt[g * 64 + tid] = run;
        }
        __syncthreads();

        const float* gsrc = (s == 0) ? g_gate1 : g_gate2;
#pragma unroll
        for (int jj = 0; jj < 4; jj++) {
            int c = warp * 4 + jj;
            int pr = (int)hist[c * 64 + myE[jj]] + myLr[jj];
            if (pr < Cd) {
                long long idx = (((long long)(g * Td + myT[jj]) * Ed + myE[jj]) * Cd + pr);
                float gate = gsrc[g * Td + myT[jj]];
                out[idx] = 1.0f;          // dispatch
                out[GTEC + idx] = gate;   // combine
            }
        }
        __syncthreads();
    }
}

// ---------------------------------------------------------------------------
// Kernel 3: finalize aux_loss and z_loss scalars.
// ---------------------------------------------------------------------------
__global__ void __launch_bounds__(64) k_final(float* __restrict__ out) {
    __shared__ float red[4];
    int tid = threadIdx.x;  // 64 threads
    float term = 0.f;
    for (int g = 0; g < Gd; g++) {
        float sp = 0.f;
        for (int bb = 0; bb < 32; bb++) sp += g_sumP_part[g * 32 + bb][tid];
        term += (float)g_cnt[g * 64 + tid] * sp;
    }
    float z = g_z_part[tid] + g_z_part[tid + 64];
#pragma unroll
    for (int o = 16; o; o >>= 1) {
        term += __shfl_xor_sync(0xffffffffu, term, o);
        z += __shfl_xor_sync(0xffffffffu, z, o);
    }
    if ((tid & 31) == 0) { red[tid >> 5] = term; red[2 + (tid >> 5)] = z; }
    __syncthreads();
    if (tid == 0) {
        float T2 = red[0] + red[1];
        float Z2 = red[2] + red[3];
        out[2 * GTEC]     = T2 * (64.0f / (4.0f * 4096.0f * 4096.0f));
        out[2 * GTEC + 1] = Z2 * (1.0f / (4.0f * 4096.0f * 64.0f));
    }
}

// ---------------------------------------------------------------------------
extern "C" void kernel_launch(void* const* d_in, const int* in_sizes, int n_in,
                              void* d_out, int out_size) {
    const float* X = (const float*)d_in[0];
    const float* W = (const float*)d_in[1];
    const float* b = (const float*)d_in[2];
    float* out = (float*)d_out;

    // k_main: GEMM blocks + async-proxy (cp.async.bulk) zero-stream blocks.
    k_main<<<NBTOT, 128>>>(X, W, b, out);
    k_route<<<Gd, 1024>>>(out);
    k_final<<<1, 64>>>(out);
}